// round 5
// baseline (speedup 1.0000x reference)
#include <cuda_runtime.h>

#define NF   128
#define NSEG 4096
#define MAXN 100000
#define MAXE 1000000

// ---- scratch (device globals: no runtime allocation allowed) ----
__device__ float    g_Pj[MAXN * NF];
__device__ float    g_Pi[MAXN * NF];    // holds Pi + bias (bias folded in epilogue)
__device__ float    g_alpha[MAXE];
__device__ unsigned g_segmax[NSEG];
__device__ float    g_segsum[NSEG];

// monotone float<->uint encoding so atomicMax works on signed floats
__device__ __forceinline__ unsigned fenc(float f) {
    unsigned b = __float_as_uint(f);
    return (b & 0x80000000u) ? ~b : (b | 0x80000000u);
}
__device__ __forceinline__ float fdec(unsigned u) {
    return __uint_as_float((u & 0x80000000u) ? (u & 0x7FFFFFFFu) : ~u);
}

__global__ void init_kernel() {
    int i = blockIdx.x * blockDim.x + threadIdx.x;
    if (i < NSEG) { g_segmax[i] = 0u; g_segsum[i] = 0.0f; }
}

// ---------------------------------------------------------------------------
// Projection GEMM: P[n, c] = sum_k X[n, k] * W[k, c],  K = N = 128.
// blockIdx.y selects (x_j,w_j)->g_Pj or (x_i,w_i)->g_Pi (+bias fold).
// 256 threads -> 128x128 tile, 8x8 thread tile. FFMA-bound.
// ---------------------------------------------------------------------------
__global__ __launch_bounds__(256)
void proj_kernel(const float* __restrict__ Xj, const float* __restrict__ Wj,
                 const float* __restrict__ Xi, const float* __restrict__ Wi,
                 const float* __restrict__ bias, int nrows) {
    const bool addb = (blockIdx.y == 1);
    const float* __restrict__ X = addb ? Xi : Xj;
    const float* __restrict__ W = addb ? Wi : Wj;
    float* __restrict__ P = addb ? g_Pi : g_Pj;

    __shared__ float xsT[32 * 129];   // [k][row], padded
    __shared__ float ws [32 * NF];    // [k][c]

    const int tid = threadIdx.x;
    const int tx  = tid & 15;
    const int ty  = tid >> 4;
    const int rowBase = blockIdx.x * 128;

    float acc[8][8];
#pragma unroll
    for (int i = 0; i < 8; i++)
#pragma unroll
        for (int j = 0; j < 8; j++) acc[i][j] = 0.0f;

    for (int kk = 0; kk < NF; kk += 32) {
#pragma unroll
        for (int p = 0; p < 4; p++) {
            int idx = p * 256 + tid;
            int row = idx >> 3;
            int kq  = idx & 7;
            int gr  = rowBase + row;
            float4 v = make_float4(0.f, 0.f, 0.f, 0.f);
            if (gr < nrows)
                v = *reinterpret_cast<const float4*>(X + gr * NF + kk + kq * 4);
            xsT[(kq * 4 + 0) * 129 + row] = v.x;
            xsT[(kq * 4 + 1) * 129 + row] = v.y;
            xsT[(kq * 4 + 2) * 129 + row] = v.z;
            xsT[(kq * 4 + 3) * 129 + row] = v.w;
        }
#pragma unroll
        for (int p = 0; p < 4; p++) {
            int idx = p * 256 + tid;
            int k  = idx >> 5;
            int cq = idx & 31;
            *reinterpret_cast<float4*>(ws + k * NF + cq * 4) =
                *reinterpret_cast<const float4*>(W + (kk + k) * NF + cq * 4);
        }
        __syncthreads();

#pragma unroll
        for (int k = 0; k < 32; k++) {
            float xv[8];
#pragma unroll
            for (int i = 0; i < 8; i++) xv[i] = xsT[k * 129 + ty * 8 + i];
            float4 w0 = *reinterpret_cast<const float4*>(ws + k * NF + tx * 4);
            float4 w1 = *reinterpret_cast<const float4*>(ws + k * NF + 64 + tx * 4);
#pragma unroll
            for (int i = 0; i < 8; i++) {
                acc[i][0] += xv[i] * w0.x;
                acc[i][1] += xv[i] * w0.y;
                acc[i][2] += xv[i] * w0.z;
                acc[i][3] += xv[i] * w0.w;
                acc[i][4] += xv[i] * w1.x;
                acc[i][5] += xv[i] * w1.y;
                acc[i][6] += xv[i] * w1.z;
                acc[i][7] += xv[i] * w1.w;
            }
        }
        __syncthreads();
    }

    float4 bv0 = make_float4(0.f, 0.f, 0.f, 0.f), bv1 = bv0;
    if (addb) {
        bv0 = *reinterpret_cast<const float4*>(bias + tx * 4);
        bv1 = *reinterpret_cast<const float4*>(bias + 64 + tx * 4);
    }
#pragma unroll
    for (int i = 0; i < 8; i++) {
        int gr = rowBase + ty * 8 + i;
        if (gr < nrows) {
            *reinterpret_cast<float4*>(P + gr * NF + tx * 4) =
                make_float4(acc[i][0] + bv0.x, acc[i][1] + bv0.y,
                            acc[i][2] + bv0.z, acc[i][3] + bv0.w);
            *reinterpret_cast<float4*>(P + gr * NF + 64 + tx * 4) =
                make_float4(acc[i][4] + bv1.x, acc[i][5] + bv1.y,
                            acc[i][6] + bv1.z, acc[i][7] + bv1.w);
        }
    }
}

// ---------------------------------------------------------------------------
// Per-edge: alpha[e] = PReLU(Pj[src] + Pi'[dst]) . mlpW + mlpb  (bias in Pi')
// 8 lanes per edge, 4 edges per warp. Each lane: 8 independent LDG.128
// (MLP=8), mlpW slice preloaded once. 3-step shfl reduce per 4 edges.
// Fused segmented max: warp pre-folds runs (sorted seg ids), then atomicMax.
// ---------------------------------------------------------------------------
__global__ __launch_bounds__(256)
void edge_alpha_kernel(const int* __restrict__ ei,
                       const int* __restrict__ seg,
                       const float* __restrict__ prelu_w,
                       const float* __restrict__ mlpW,
                       const float* __restrict__ mlpb, int E) {
    const int warp = (blockIdx.x * blockDim.x + threadIdx.x) >> 5;
    const int lane = threadIdx.x & 31;
    const int sub  = lane >> 3;      // edge within warp (0..3)
    const int sl   = lane & 7;       // 16-float slice within edge
    const int e0   = warp * 4;
    if (e0 >= E) return;

    const int  e     = e0 + sub;
    const bool valid = (e < E);
    const int  ec    = valid ? e : (E - 1);

    // preload mlp weight slice (reused across nothing here, but stays in regs
    // instead of 8 extra L1 wavefronts per edge as in v1)
    const float4* wp = reinterpret_cast<const float4*>(mlpW + sl * 16);
    float4 w0 = wp[0], w1 = wp[1], w2 = wp[2], w3 = wp[3];
    float pw = prelu_w[0];
    float mb = mlpb[0];

    int src = ei[ec];
    int dst = ei[E + ec];
    int sg  = seg[ec];

    const float4* pj = reinterpret_cast<const float4*>(g_Pj + src * NF + sl * 16);
    const float4* pi = reinterpret_cast<const float4*>(g_Pi + dst * NF + sl * 16);
    // issue all 8 gathers before consuming (MLP=8)
    float4 a0 = pj[0], a1 = pj[1], a2 = pj[2], a3 = pj[3];
    float4 b0 = pi[0], b1 = pi[1], b2 = pi[2], b3 = pi[3];

    float s = 0.0f;
#define ACCQ(A, B, Wv)                                            \
    { float h;                                                    \
      h = A.x + B.x; h = (h >= 0.f) ? h : pw * h; s += h * Wv.x;  \
      h = A.y + B.y; h = (h >= 0.f) ? h : pw * h; s += h * Wv.y;  \
      h = A.z + B.z; h = (h >= 0.f) ? h : pw * h; s += h * Wv.z;  \
      h = A.w + B.w; h = (h >= 0.f) ? h : pw * h; s += h * Wv.w; }
    ACCQ(a0, b0, w0)
    ACCQ(a1, b1, w1)
    ACCQ(a2, b2, w2)
    ACCQ(a3, b3, w3)
#undef ACCQ

    // reduce across the 8 lanes of this edge
    s += __shfl_xor_sync(0xffffffffu, s, 1);
    s += __shfl_xor_sync(0xffffffffu, s, 2);
    s += __shfl_xor_sync(0xffffffffu, s, 4);

    float alpha = s + mb;
    if (sl == 0 && valid) g_alpha[e] = alpha;

    // ---- fused segmented max (seg ids sorted => runs are contiguous) ----
    float av = valid ? alpha : -3.4e38f;
    // fold across the 4 sub-edges (live values sit on lanes 0,8,16,24)
#pragma unroll
    for (int o = 8; o <= 16; o <<= 1) {
        float a2v = __shfl_down_sync(0xffffffffu, av, o);
        int   s2v = __shfl_down_sync(0xffffffffu, sg, o);
        if (lane + o < 32 && s2v == sg) av = fmaxf(av, a2v);
    }
    int sp = __shfl_up_sync(0xffffffffu, sg, 8);
    bool head = (lane == 0) || (sp != sg);
    if (sl == 0 && valid && head) atomicMax(&g_segmax[sg], fenc(av));
}

// e = exp(alpha - segmax); store to out; warp-segmented suffix-sum + atomicAdd
__global__ __launch_bounds__(256)
void expsum_kernel(const int* __restrict__ seg, float* __restrict__ out, int E) {
    int i    = blockIdx.x * blockDim.x + threadIdx.x;
    int lane = threadIdx.x & 31;
    float e = 0.0f;
    int   s = -1;
    if (i < E) {
        s = seg[i];
        float m = fdec(g_segmax[s]);
        e = __expf(g_alpha[i] - m);
        out[i] = e;
    }
    float sum = e;
#pragma unroll
    for (int o = 1; o < 32; o <<= 1) {
        float av = __shfl_down_sync(0xffffffffu, sum, o);
        int   sv = __shfl_down_sync(0xffffffffu, s, o);
        if (lane + o < 32 && sv == s) sum += av;
    }
    int sp = __shfl_up_sync(0xffffffffu, s, 1);
    bool head = (lane == 0) || (sp != s);
    if (i < E && head) atomicAdd(&g_segsum[s], sum);
}

__global__ __launch_bounds__(256)
void norm_kernel(const int* __restrict__ seg, float* __restrict__ out, int E) {
    int i = blockIdx.x * blockDim.x + threadIdx.x;
    if (i < E) out[i] = out[i] / (g_segsum[seg[i]] + 1e-16f);
}

// ---------------------------------------------------------------------------
extern "C" void kernel_launch(void* const* d_in, const int* in_sizes, int n_in,
                              void* d_out, int out_size) {
    const float* x_j   = (const float*)d_in[0];
    const float* x_i   = (const float*)d_in[1];
    const int*   ei    = (const int*)  d_in[2];
    const int*   seg   = (const int*)  d_in[3];
    const float* w_j   = (const float*)d_in[4];
    const float* w_i   = (const float*)d_in[5];
    const float* bias  = (const float*)d_in[6];
    const float* prelu = (const float*)d_in[7];
    const float* mlpW  = (const float*)d_in[8];
    const float* mlpb  = (const float*)d_in[9];

    int nnodes = in_sizes[0] / NF;
    int E      = in_sizes[3];
    float* out = (float*)d_out;

    init_kernel<<<(NSEG + 255) / 256, 256>>>();

    dim3 pg((nnodes + 127) / 128, 2);
    proj_kernel<<<pg, 256>>>(x_j, w_j, x_i, w_i, bias, nnodes);

    // 4 edges per warp -> E/4 warps -> E*8 threads
    long long nthreads = (long long)((E + 3) / 4) * 32;
    edge_alpha_kernel<<<(unsigned)((nthreads + 255) / 256), 256>>>(
        ei, seg, prelu, mlpW, mlpb, E);

    int eb = (E + 255) / 256;
    expsum_kernel<<<eb, 256>>>(seg, out, E);
    norm_kernel  <<<eb, 256>>>(seg, out, E);
}